// round 8
// baseline (speedup 1.0000x reference)
#include <cuda_runtime.h>

// LSTM_46316927320185 — R8: vocab table + full-warp K-split recurrence
// B=4096, T=512, EMB=32, HID=16, VOCAB=50000.
//
// R7 (200.7us; recur 177): recur stall-bound at 3.5 warps/SMSP (issue 45%).
// Warp count was pinned by 16 lanes/elem. R8 K-splits the recurrence across
// the whole warp: warp = 1 elem, lane (gp=lane>>4, j=lane&15) computes unit
// j's gates over HALF of h (8 k = 16 fma2), merged by 4 shfl_xor(16)+add.
// -> 4096 warps (~7/SMSP, 2x R7), ~51 instrs/warp-step, regs halved.
// Table phase unchanged (12.8MB gate-preactivation table, L2-resident).

#define HID    16
#define EMB    32
#define T_LEN  512
#define BATCH  4096
#define VOCAB  50000

typedef unsigned long long u64;

// [v*HID + j] -> float4 (xp_i, xp_f, xp_g, xp_o) with b_ih+b_hh folded. 12.8 MB.
__device__ float4 g_tbl[(size_t)VOCAB * HID];

__device__ __forceinline__ u64 fma2(u64 a, u64 b, u64 c) {
    u64 d; asm("fma.rn.f32x2 %0, %1, %2, %3;" : "=l"(d) : "l"(a), "l"(b), "l"(c)); return d;
}
__device__ __forceinline__ u64 rep2(float v) {
    u64 r; asm("mov.b64 %0, {%1, %1};" : "=l"(r) : "f"(v)); return r;
}
__device__ __forceinline__ void unpack2(u64 v, float& lo, float& hi) {
    asm("mov.b64 {%0, %1}, %2;" : "=f"(lo), "=f"(hi) : "l"(v));
}
__device__ __forceinline__ float hadd2(u64 v) {
    float lo, hi; unpack2(v, lo, hi); return lo + hi;
}
__device__ __forceinline__ float tanh_ap(float x) {
    float y; asm("tanh.approx.f32 %0, %1;" : "=f"(y) : "f"(x)); return y;
}
__device__ __forceinline__ float sig_ap(float x) {
    return fmaf(tanh_ap(0.5f * x), 0.5f, 0.5f);
}

// ============ Phase A: per-vocab projection table ============
#define PT_THREADS 256
#define PT_GRID    ((VOCAB * HID) / PT_THREADS)   // 3125

__global__ __launch_bounds__(PT_THREADS)
void proj_table_kernel(const float* __restrict__ embed,
                       const float* __restrict__ w_ih,
                       const float* __restrict__ b_ih,
                       const float* __restrict__ b_hh)
{
    // gate-packed transposed weights: [k*HID+j] = ((wi,wf),(wg,wo))
    __shared__ ulonglong2 w_u[EMB * HID];   // 8 KB

    const int tid = threadIdx.x;
    for (int i = tid; i < EMB * HID; i += PT_THREADS) {
        int k = i / HID, jj = i % HID;
        float4 w = make_float4(w_ih[(0 * HID + jj) * EMB + k],
                               w_ih[(1 * HID + jj) * EMB + k],
                               w_ih[(2 * HID + jj) * EMB + k],
                               w_ih[(3 * HID + jj) * EMB + k]);
        *(float4*)&w_u[i] = w;
    }
    __syncthreads();

    const int gid = blockIdx.x * PT_THREADS + tid;
    const int v = gid >> 4;        // vocab row
    const int j = gid & 15;        // hidden unit

    const float* er = embed + (size_t)v * EMB;
    u64 a01 = 0ull, a23 = 0ull;
    #pragma unroll
    for (int k = 0; k < EMB; ++k) {
        const u64 q = rep2(er[k]);              // broadcast across 16 j-lanes
        const ulonglong2 w = w_u[k * HID + j];
        a01 = fma2(q, w.x, a01);
        a23 = fma2(q, w.y, a23);
    }
    float ai, af, ag, ao;
    unpack2(a01, ai, af);
    unpack2(a23, ag, ao);
    g_tbl[gid] = make_float4(ai + b_ih[j]           + b_hh[j],
                             af + b_ih[HID + j]     + b_hh[HID + j],
                             ag + b_ih[2 * HID + j] + b_hh[2 * HID + j],
                             ao + b_ih[3 * HID + j] + b_hh[3 * HID + j]);
}

// ============ Phase B: recurrence — warp = 1 elem, K split across halves ============
#define B_THREADS 128
#define B_WARPS   4
#define B_ELEMS   4                     // 1 per warp
#define B_GRID    (BATCH / B_ELEMS)     // 1024

__global__ __launch_bounds__(B_THREADS, 7)
void recur_kernel(const int*   __restrict__ x,
                  const float* __restrict__ w_hh,
                  const float* __restrict__ fc_w,
                  const float* __restrict__ fc_b,
                  float*       __restrict__ out)
{
    // double-buffered h staging: [buf][warp(elem)][j]; j-pairs contiguous -> u64
    __shared__ float h_s[2][B_WARPS][HID];

    const int tid  = threadIdx.x;
    const int warp = tid >> 5, lane = tid & 31;
    const int gp   = lane >> 4;          // K half: h k in [gp*8, gp*8+8)
    const int j    = lane & 15;          // hidden unit owned
    const int b    = blockIdx.x * B_ELEMS + warp;

    // this half's K-pair packed recurrent weights: wk[g][i] = (w[g,j,gp*8+2i], ..+2i+1)
    u64 wk[4][4];
    #pragma unroll
    for (int g = 0; g < 4; ++g) {
        const u64* wr = (const u64*)(w_hh + (size_t)(g * HID + j) * HID + gp * 8);
        #pragma unroll
        for (int i = 0; i < 4; ++i) wk[g][i] = wr[i];
    }

    const int* xcol = x + (size_t)b * T_LEN;

    // gather pipeline: xp rows for t (xc) and t+1 (xn); index for t+2 (i2)
    float4 xc = g_tbl[(size_t)xcol[0] * HID + j];
    float4 xn = g_tbl[(size_t)xcol[1] * HID + j];
    int    i2 = xcol[2];

    float h = 0.f, c = 0.f;

    #pragma unroll 4
    for (int t = 0; t < T_LEN; ++t) {
        const int buf = t & 1;
        if (gp == 0) h_s[buf][warp][j] = h;   // halves hold identical h; one writes
        __syncwarp();

        // kick next gathers early
        const float4 x2 = g_tbl[(size_t)i2 * HID + j];
        const int    i3 = xcol[(t + 3 < T_LEN) ? (t + 3) : (T_LEN - 1)];

        // this half's 8 h values as 2 ready-packed ulonglong2 (broadcast LDS)
        const ulonglong2* hp = (const ulonglong2*)&h_s[buf][warp][gp * 8];
        const ulonglong2 hv0 = hp[0];
        const ulonglong2 hv1 = hp[1];

        u64 a0 = 0ull, a1 = 0ull, a2 = 0ull, a3 = 0ull;
        a0 = fma2(hv0.x, wk[0][0], a0); a0 = fma2(hv0.y, wk[0][1], a0);
        a0 = fma2(hv1.x, wk[0][2], a0); a0 = fma2(hv1.y, wk[0][3], a0);
        a1 = fma2(hv0.x, wk[1][0], a1); a1 = fma2(hv0.y, wk[1][1], a1);
        a1 = fma2(hv1.x, wk[1][2], a1); a1 = fma2(hv1.y, wk[1][3], a1);
        a2 = fma2(hv0.x, wk[2][0], a2); a2 = fma2(hv0.y, wk[2][1], a2);
        a2 = fma2(hv1.x, wk[2][2], a2); a2 = fma2(hv1.y, wk[2][3], a2);
        a3 = fma2(hv0.x, wk[3][0], a3); a3 = fma2(hv0.y, wk[3][1], a3);
        a3 = fma2(hv1.x, wk[3][2], a3); a3 = fma2(hv1.y, wk[3][3], a3);

        // partial sums for this half, then merge halves via shfl_xor(16)
        float s0 = hadd2(a0), s1 = hadd2(a1), s2 = hadd2(a2), s3 = hadd2(a3);
        s0 += __shfl_xor_sync(0xffffffffu, s0, 16);
        s1 += __shfl_xor_sync(0xffffffffu, s1, 16);
        s2 += __shfl_xor_sync(0xffffffffu, s2, 16);
        s3 += __shfl_xor_sync(0xffffffffu, s3, 16);

        const float si = s0 + xc.x;
        const float sf = s1 + xc.y;
        const float sg = s2 + xc.z;
        const float so = s3 + xc.w;

        xc = xn; xn = x2; i2 = i3;

        const float ig = sig_ap(si), fg = sig_ap(sf);
        const float gg = tanh_ap(sg), og = sig_ap(so);
        c = fg * c + ig * gg;
        h = og * tanh_ap(c);     // identical in both halves (same fp ops)
    }

    // FC head: reduce over j (within each 16-lane half; redundant across halves)
    float v = h * fc_w[j];
    v += __shfl_xor_sync(0xffffffffu, v, 8);
    v += __shfl_xor_sync(0xffffffffu, v, 4);
    v += __shfl_xor_sync(0xffffffffu, v, 2);
    v += __shfl_xor_sync(0xffffffffu, v, 1);
    if (lane == 0) out[b] = sig_ap(v + fc_b[0]);
}

extern "C" void kernel_launch(void* const* d_in, const int* in_sizes, int n_in,
                              void* d_out, int out_size)
{
    const int*   x     = (const int*)  d_in[0];
    const float* embed = (const float*)d_in[1];
    const float* w_ih  = (const float*)d_in[2];
    const float* w_hh  = (const float*)d_in[3];
    const float* b_ih  = (const float*)d_in[4];
    const float* b_hh  = (const float*)d_in[5];
    const float* fc_w  = (const float*)d_in[6];
    const float* fc_b  = (const float*)d_in[7];
    float* out = (float*)d_out;

    proj_table_kernel<<<PT_GRID, PT_THREADS>>>(embed, w_ih, b_ih, b_hh);
    recur_kernel<<<B_GRID, B_THREADS>>>(x, w_hh, fc_w, fc_b, out);
}

// round 10
// speedup vs baseline: 1.3634x; 1.3634x over previous
#include <cuda_runtime.h>

// LSTM_46316927320185 — R9 resubmit (prior run lost to infra failure)
// B=4096, T=512, EMB=32, HID=16, VOCAB=50000.
//
// R8 regressed (246us): K-split raised warp-instrs/elem-step ~1.6x; at 59% issue
// the extra occupancy couldn't pay for +46% instructions. R7's mapping
// (warp = 2 elems, full-K per lane, no merge shfl) is the instruction-count
// optimum. This version keeps it and fixes R7's residuals:
//  (1) grid 148 x 448thr (14 warps, 28 elems) = exactly 1 CTA/SM — removes the
//      4-vs-3 CTA wave imbalance that set R7's makespan (68 SMs ran 16 warps).
//  (2) sigmoid input halving folded into data: table stores gates i,f,o
//      pre-scaled by 0.5; recur halves wk[i],wk[f],wk[o] once at init.
//      sig = fmaf(tanh.approx(s), 0.5, 0.5) with zero per-step scaling FMULs.

#define HID    16
#define EMB    32
#define T_LEN  512
#define BATCH  4096
#define VOCAB  50000

typedef unsigned long long u64;

// [v*HID + j] -> float4 (xp_i/2, xp_f/2, xp_g, xp_o/2), biases folded. 12.8 MB.
__device__ float4 g_tbl[(size_t)VOCAB * HID];

__device__ __forceinline__ u64 fma2(u64 a, u64 b, u64 c) {
    u64 d; asm("fma.rn.f32x2 %0, %1, %2, %3;" : "=l"(d) : "l"(a), "l"(b), "l"(c)); return d;
}
__device__ __forceinline__ u64 mul2(u64 a, u64 b) {
    u64 d; asm("mul.rn.f32x2 %0, %1, %2;" : "=l"(d) : "l"(a), "l"(b)); return d;
}
__device__ __forceinline__ u64 rep2(float v) {
    u64 r; asm("mov.b64 %0, {%1, %1};" : "=l"(r) : "f"(v)); return r;
}
__device__ __forceinline__ void unpack2(u64 v, float& lo, float& hi) {
    asm("mov.b64 {%0, %1}, %2;" : "=f"(lo), "=f"(hi) : "l"(v));
}
__device__ __forceinline__ float hadd2(u64 v) {
    float lo, hi; unpack2(v, lo, hi); return lo + hi;
}
__device__ __forceinline__ float tanh_ap(float x) {
    float y; asm("tanh.approx.f32 %0, %1;" : "=f"(y) : "f"(x)); return y;
}

// ============ Phase A: per-vocab projection table ============
#define PT_THREADS 256
#define PT_GRID    ((VOCAB * HID) / PT_THREADS)   // 3125

__global__ __launch_bounds__(PT_THREADS)
void proj_table_kernel(const float* __restrict__ embed,
                       const float* __restrict__ w_ih,
                       const float* __restrict__ b_ih,
                       const float* __restrict__ b_hh)
{
    // gate-packed transposed weights: [k*HID+j] = ((wi,wf),(wg,wo))
    __shared__ ulonglong2 w_u[EMB * HID];   // 8 KB

    const int tid = threadIdx.x;
    for (int i = tid; i < EMB * HID; i += PT_THREADS) {
        int k = i / HID, jj = i % HID;
        float4 w = make_float4(w_ih[(0 * HID + jj) * EMB + k],
                               w_ih[(1 * HID + jj) * EMB + k],
                               w_ih[(2 * HID + jj) * EMB + k],
                               w_ih[(3 * HID + jj) * EMB + k]);
        *(float4*)&w_u[i] = w;
    }
    __syncthreads();

    const int gid = blockIdx.x * PT_THREADS + tid;
    const int v = gid >> 4;        // vocab row
    const int j = gid & 15;        // hidden unit

    const float* er = embed + (size_t)v * EMB;
    u64 a01 = 0ull, a23 = 0ull;
    #pragma unroll
    for (int k = 0; k < EMB; ++k) {
        const u64 q = rep2(er[k]);              // broadcast across 16 j-lanes
        const ulonglong2 w = w_u[k * HID + j];
        a01 = fma2(q, w.x, a01);
        a23 = fma2(q, w.y, a23);
    }
    float ai, af, ag, ao;
    unpack2(a01, ai, af);
    unpack2(a23, ag, ao);
    // gates i,f,o pre-scaled by 0.5 (sigmoid identity); g unscaled (tanh)
    g_tbl[gid] = make_float4(0.5f * (ai + b_ih[j]           + b_hh[j]),
                             0.5f * (af + b_ih[HID + j]     + b_hh[HID + j]),
                                     ag + b_ih[2 * HID + j] + b_hh[2 * HID + j],
                             0.5f * (ao + b_ih[3 * HID + j] + b_hh[3 * HID + j]));
}

// ============ Phase B: recurrence — warp = 2 elems, full-K, uniform grid ============
#define RC_WARPS   14
#define RC_THREADS 448                 // 14 warps -> exactly 1 CTA per SM
#define RC_EPC     28                  // 2 elems per warp
#define RC_GRID    148                 // 148*28 = 4144 >= 4096 (tail clamped)

__global__ __launch_bounds__(RC_THREADS, 1)
void recur_kernel(const int*   __restrict__ x,
                  const float* __restrict__ w_hh,
                  const float* __restrict__ fc_w,
                  const float* __restrict__ fc_b,
                  float*       __restrict__ out)
{
    // double-buffered h staging: [buf][warp][elem][j] (j-pairs contiguous -> u64)
    __shared__ float h_s[2][RC_WARPS][2][HID];

    const int tid  = threadIdx.x;
    const int warp = tid >> 5, lane = tid & 31;
    const int eh   = lane >> 4;          // which of the warp's 2 elems
    const int j    = lane & 15;          // hidden unit owned
    const int b    = blockIdx.x * RC_EPC + warp * 2 + eh;
    const int bc   = (b < BATCH) ? b : (BATCH - 1);   // clamp (dummies masked at store)

    // K-pair packed recurrent weights: wk[g][i] = (w[g,j,2i], w[g,j,2i+1]);
    // gates i,f,o halved once here (sigmoid scale folding).
    u64 wk[4][8];
    #pragma unroll
    for (int g = 0; g < 4; ++g) {
        const u64* wr = (const u64*)(w_hh + (size_t)(g * HID + j) * HID);
        #pragma unroll
        for (int i = 0; i < 8; ++i) wk[g][i] = wr[i];
    }
    {
        const u64 hlf = rep2(0.5f);
        #pragma unroll
        for (int i = 0; i < 8; ++i) {
            wk[0][i] = mul2(wk[0][i], hlf);
            wk[1][i] = mul2(wk[1][i], hlf);
            wk[3][i] = mul2(wk[3][i], hlf);
        }
    }

    const int* xcol = x + (size_t)bc * T_LEN;

    // gather pipeline: table rows for t (xc), t+1 (xn); index for t+2 (i2)
    float4 xc = g_tbl[(size_t)xcol[0] * HID + j];
    float4 xn = g_tbl[(size_t)xcol[1] * HID + j];
    int    i2 = xcol[2];

    float h = 0.f, c = 0.f;

    #pragma unroll 4
    for (int t = 0; t < T_LEN; ++t) {
        const int buf = t & 1;
        h_s[buf][warp][eh][j] = h;
        __syncwarp();

        // kick next gathers early (t+2 row; t+3 index)
        const float4 x2 = g_tbl[(size_t)i2 * HID + j];
        const int    i3 = xcol[(t + 3 < T_LEN) ? (t + 3) : (T_LEN - 1)];

        // own elem's 16 h values as 4 ready-packed ulonglong2 (broadcast LDS)
        const ulonglong2* hp = (const ulonglong2*)h_s[buf][warp][eh];
        u64 a0 = 0ull, a1 = 0ull, a2 = 0ull, a3 = 0ull;
        #pragma unroll
        for (int i = 0; i < 4; ++i) {
            const ulonglong2 hv = hp[i];
            a0 = fma2(hv.x, wk[0][2 * i], a0); a0 = fma2(hv.y, wk[0][2 * i + 1], a0);
            a1 = fma2(hv.x, wk[1][2 * i], a1); a1 = fma2(hv.y, wk[1][2 * i + 1], a1);
            a2 = fma2(hv.x, wk[2][2 * i], a2); a2 = fma2(hv.y, wk[2][2 * i + 1], a2);
            a3 = fma2(hv.x, wk[3][2 * i], a3); a3 = fma2(hv.y, wk[3][2 * i + 1], a3);
        }

        const float si = hadd2(a0) + xc.x;   // already scaled by 0.5
        const float sf = hadd2(a1) + xc.y;
        const float sg = hadd2(a2) + xc.z;   // unscaled (tanh gate)
        const float so = hadd2(a3) + xc.w;

        xc = xn; xn = x2; i2 = i3;

        const float ig = fmaf(tanh_ap(si), 0.5f, 0.5f);
        const float fg = fmaf(tanh_ap(sf), 0.5f, 0.5f);
        const float gg = tanh_ap(sg);
        const float og = fmaf(tanh_ap(so), 0.5f, 0.5f);
        c = fg * c + ig * gg;
        h = og * tanh_ap(c);
    }

    // FC head: reduce over j within this elem's 16-lane half
    float v = h * fc_w[j];
    v += __shfl_xor_sync(0xffffffffu, v, 8);
    v += __shfl_xor_sync(0xffffffffu, v, 4);
    v += __shfl_xor_sync(0xffffffffu, v, 2);
    v += __shfl_xor_sync(0xffffffffu, v, 1);
    if (j == 0 && b < BATCH)
        out[b] = fmaf(tanh_ap(0.5f * (v + fc_b[0])), 0.5f, 0.5f);
}

extern "C" void kernel_launch(void* const* d_in, const int* in_sizes, int n_in,
                              void* d_out, int out_size)
{
    const int*   x     = (const int*)  d_in[0];
    const float* embed = (const float*)d_in[1];
    const float* w_ih  = (const float*)d_in[2];
    const float* w_hh  = (const float*)d_in[3];
    const float* b_ih  = (const float*)d_in[4];
    const float* b_hh  = (const float*)d_in[5];
    const float* fc_w  = (const float*)d_in[6];
    const float* fc_b  = (const float*)d_in[7];
    float* out = (float*)d_out;

    proj_table_kernel<<<PT_GRID, PT_THREADS>>>(embed, w_ih, b_ih, b_hh);
    recur_kernel<<<RC_GRID, RC_THREADS>>>(x, w_hh, fc_w, fc_b, out);
}